// round 8
// baseline (speedup 1.0000x reference)
#include <cuda_runtime.h>
#include <cuda_fp16.h>
#include <stdint.h>
#include <math.h>

#define Bsz 512
#define Tsz 128
#define Hsz 512
#define Vsz 512
#define NBT 65536
#define G4  2048

// ---------------- device scratch ----------------
__device__ __align__(128) __half g_inp[(size_t)NBT*Hsz];
__device__ __align__(128) __half g_seq[(size_t)NBT*Hsz];
__device__ __align__(128) __half g_xgT[(size_t)Tsz*G4*Bsz];   // [t][n][b] fp16
__device__ __align__(128) __half g_h0[Bsz*Hsz], g_h1[Bsz*Hsz];
__device__ __align__(128) float  g_c[Bsz*Hsz];
__device__ __align__(128) __half g_Wih[2*(size_t)G4*Hsz];
__device__ __align__(128) __half g_Whh[2*(size_t)G4*Hsz];
__device__ __align__(128) __half g_dW[(size_t)Vsz*Hsz];
__device__ unsigned g_gen[4], g_cnt[4];

// ---------------- helpers ----------------
__device__ __forceinline__ uint32_t smem_u32(const void* p){
    uint32_t a; asm("{ .reg .u64 t; cvta.to.shared.u64 t, %1; cvt.u32.u64 %0, t; }" : "=r"(a) : "l"(p)); return a;
}
#define CP16(dst, src) asm volatile("cp.async.cg.shared.global [%0], [%1], 16;" :: "r"(dst), "l"(src))
#define CPCOMMIT()     asm volatile("cp.async.commit_group;" ::: "memory")
#define CPWAIT(n)      asm volatile("cp.async.wait_group %0;" :: "n"(n) : "memory")
#define LDSM4(r, a) asm volatile("ldmatrix.sync.aligned.m8n8.x4.shared.b16 {%0,%1,%2,%3}, [%4];" \
    : "=r"((r)[0]),"=r"((r)[1]),"=r"((r)[2]),"=r"((r)[3]) : "r"(a))

__device__ __forceinline__ void mma16816(float* d, const uint32_t* a, const uint32_t* b){
    asm volatile("mma.sync.aligned.m16n8k16.row.col.f32.f16.f16.f32 "
        "{%0,%1,%2,%3}, {%4,%5,%6,%7}, {%8,%9}, {%0,%1,%2,%3};"
        : "+f"(d[0]), "+f"(d[1]), "+f"(d[2]), "+f"(d[3])
        : "r"(a[0]), "r"(a[1]), "r"(a[2]), "r"(a[3]), "r"(b[0]), "r"(b[1]));
}

// ============ generic FF GEMM (fp16 operands, fp32 accum) ============
// BK=64: chunk = 128 rows x 64 fp16 (32 words, padded to 36). A then B.
#define CHW 4608                    // words per matrix per chunk
#define STW 9216                    // words per stage
#define SMEMB 110592                // 3 stages

__device__ __forceinline__ void load_chunk(uint32_t sbase,
    const __half* __restrict__ A, const __half* __restrict__ B,
    int m0, int n0, int ck, int bmap, int tid)
{
    #pragma unroll
    for (int i = tid; i < 1024; i += 256) {
        int r = i >> 3, q = i & 7;
        CP16(sbase + (r*36 + q*4)*4, A + (size_t)(m0 + r)*Hsz + ck*64 + q*8);
    }
    #pragma unroll
    for (int i = tid; i < 1024; i += 256) {
        int r = i >> 3, q = i & 7;
        int brow;
        if (bmap == 0)      brow = n0 + r;
        else                { int c = n0 + r; brow = (c & 511)*Tsz + (c >> 9); }
        CP16(sbase + (CHW + r*36 + q*4)*4, B + (size_t)brow*Hsz + ck*64 + q*8);
    }
    CPCOMMIT();
}

__device__ __forceinline__ void compute_chunk(uint32_t stg,
    float acc[4][4][4], int lane, int wm, int wn)
{
    int laneA_r = lane & 15;
    int laneA_c = (lane >> 4) * 4;
    int laneB_r = (lane & 7) + ((lane >> 4) << 3);
    int laneB_c = ((lane >> 3) & 1) * 4;
    #pragma unroll
    for (int ks = 0; ks < 4; ks++) {
        int kw = ks*8;
        uint32_t ah[4][4], bh[2][4];
        #pragma unroll
        for (int mt = 0; mt < 4; mt++) {
            uint32_t aw = (uint32_t)(wm*64 + mt*16 + laneA_r)*36 + kw + laneA_c;
            LDSM4(ah[mt], stg + aw*4);
        }
        #pragma unroll
        for (int np = 0; np < 2; np++) {
            uint32_t bw = (uint32_t)(wn*32 + np*16 + laneB_r)*36 + kw + laneB_c;
            LDSM4(bh[np], stg + (CHW + bw)*4);
        }
        #pragma unroll
        for (int mt = 0; mt < 4; mt++)
        #pragma unroll
        for (int nt = 0; nt < 4; nt++)
            mma16816(acc[mt][nt], ah[mt], &bh[nt>>1][(nt&1)*2]);
    }
}

__global__ void __launch_bounds__(256)
gemm_mma(const __half* __restrict__ A, const __half* __restrict__ B,
         const float* __restrict__ br1, const float* __restrict__ br2,
         const float* __restrict__ bcn, void* __restrict__ Cv,
         int Ntot, int bmap, int mx, int cmode)
{
    extern __shared__ uint32_t sm[];
    uint32_t sbase = smem_u32(sm);
    int tid = threadIdx.x, lane = tid & 31, wid = tid >> 5;
    int wm = wid >> 2, wn = wid & 3;
    int bm = mx ? blockIdx.x : blockIdx.y;
    int bn = mx ? blockIdx.y : blockIdx.x;
    int m0 = bm*128, n0 = bn*128;

    float acc[4][4][4];
    #pragma unroll
    for (int a = 0; a < 4; a++)
    #pragma unroll
    for (int b = 0; b < 4; b++)
    #pragma unroll
    for (int cc = 0; cc < 4; cc++) acc[a][b][cc] = 0.f;

    load_chunk(sbase, A, B, m0, n0, 0, bmap, tid);
    int st = 0, nst = 1;
    for (int k = 0; k < 8; k++) {
        if (k < 7) {
            load_chunk(sbase + nst*STW*4, A, B, m0, n0, k+1, bmap, tid);
            CPWAIT(1);
        } else {
            CPWAIT(0);
        }
        __syncthreads();
        compute_chunk(sbase + st*STW*4, acc, lane, wm, wn);
        st = nst; nst = (nst + 1 == 3) ? 0 : nst + 1;
    }

    #pragma unroll
    for (int mt = 0; mt < 4; mt++) {
        #pragma unroll
        for (int half = 0; half < 2; half++) {
            int m = m0 + wm*64 + mt*16 + (lane >> 2) + half*8;
            float rb = br1 ? (br1[m] + br2[m]) : 0.f;
            #pragma unroll
            for (int nt = 0; nt < 4; nt++) {
                int c = n0 + wn*32 + nt*8 + (lane & 3)*2;
                float v0 = acc[mt][nt][half*2+0] + rb;
                float v1 = acc[mt][nt][half*2+1] + rb;
                if (bcn) { v0 += bcn[c]; v1 += bcn[c+1]; }
                if (cmode) {
                    __half* dst = (__half*)Cv + ((size_t)(c >> 9)*G4 + m)*Bsz + (c & 511);
                    __half2 hv; hv.x = __float2half_rn(v0); hv.y = __float2half_rn(v1);
                    *(__half2*)dst = hv;
                } else {
                    *(float2*)((float*)Cv + (size_t)m*Ntot + c) = make_float2(v0, v1);
                }
            }
        }
    }
}

// ============ persistent LSTM recurrence (fp16) ============
// grid (32,4): x -> 16 units (u0), y -> 128 batch (b0). Group barrier per y.
// BK=64, 8 chunks, 3-stage h pipeline, row pad 36 words.
#define PS_SMEM 129536
__device__ __forceinline__ int WOFFf(int ck,int r){ return (ck*64 + r)*36; }
__device__ __forceinline__ int HOFFf(int st,int r){ return 18432 + (st*128 + r)*36; }

__global__ void reset_bar(){ int i = threadIdx.x; if (i < 4) { g_gen[i] = 0; g_cnt[i] = 0; } }

__global__ void __launch_bounds__(256,1)
lstm_persist(const __half* __restrict__ xg, const __half* __restrict__ W,
             __half* __restrict__ h0, __half* __restrict__ h1,
             float* __restrict__ cst, __half* __restrict__ seq)
{
    extern __shared__ uint32_t sm[];
    uint32_t sb = smem_u32(sm);
    int tid = threadIdx.x, lane = tid & 31, w = tid >> 5;
    int laneR = lane >> 2, laneC = lane & 3;
    int u0 = blockIdx.x * 16;
    int b0 = blockIdx.y * 128;
    int gid = blockIdx.y;
    unsigned nGrp = gridDim.x;

    int laneA_r = lane & 15;
    int laneA_c = (lane >> 4) * 4;
    int laneB_r = (lane & 7) + ((lane >> 4) << 3);
    int laneB_c = ((lane >> 3) & 1) * 4;

    // ---- persistent W tile: rows n = g*16+ul -> Whh row g*512 + u0+ul ----
    for (int i = tid; i < 4096; i += 256) {
        int ck = i >> 9, rem = i & 511;
        int r = rem >> 3, q = rem & 7;
        int g = r >> 4, ul = r & 15;
        CP16(sb + (WOFFf(ck,r) + q*4)*4,
             W + ((size_t)(g*Hsz + u0 + ul))*Hsz + ck*64 + q*8);
    }
    CPCOMMIT(); CPWAIT(0);
    __syncthreads();

    __half* hb[2] = {h0, h1};

    for (int t = 0; t < Tsz; t++) {
        const __half* Hc = hb[t & 1];
        __half* Nx = hb[(t+1) & 1];

        // prefetch xg (independent of h)
        float xv[2][16];
        {
            const __half* xgt = xg + (size_t)t*G4*Bsz;
            #pragma unroll
            for (int half = 0; half < 2; half++) {
                int b = b0 + w*16 + laneR + half*8;
                #pragma unroll
                for (int uh = 0; uh < 2; uh++)
                #pragma unroll
                for (int du = 0; du < 2; du++) {
                    int u = u0 + laneC*2 + uh*8 + du;
                    #pragma unroll
                    for (int g = 0; g < 4; g++)
                        xv[half][uh*8 + du*4 + g] =
                            __half2float(xgt[((size_t)(g*Hsz + u))*Bsz + b]);
                }
            }
        }

        float acc[8][4];
        #pragma unroll
        for (int i = 0; i < 8; i++)
        #pragma unroll
        for (int j = 0; j < 4; j++) acc[i][j] = 0.f;

        auto ldh = [&](int ck, int st){
            #pragma unroll
            for (int i = tid; i < 1024; i += 256) {
                int r = i >> 3, q = i & 7;
                CP16(sb + (HOFFf(st,r) + q*4)*4, Hc + (size_t)(b0 + r)*Hsz + ck*64 + q*8);
            }
            CPCOMMIT();
        };

        ldh(0, 0);
        int st = 0, nst = 1;
        for (int ck = 0; ck < 8; ck++) {
            if (ck < 7) { ldh(ck+1, nst); CPWAIT(1); } else { CPWAIT(0); }
            __syncthreads();
            #pragma unroll
            for (int ks = 0; ks < 4; ks++) {
                int kw = ks*8;
                uint32_t ah[4], bh[4][4];
                uint32_t aw = (uint32_t)(HOFFf(st, w*16 + laneA_r)) + kw + laneA_c;
                LDSM4(ah, sb + aw*4);
                #pragma unroll
                for (int np = 0; np < 4; np++) {
                    uint32_t bw = (uint32_t)(WOFFf(ck, np*16 + laneB_r)) + kw + laneB_c;
                    LDSM4(bh[np], sb + bw*4);
                }
                #pragma unroll
                for (int nt = 0; nt < 8; nt++)
                    mma16816(acc[nt], ah, &bh[nt>>1][(nt&1)*2]);
            }
            st = nst; nst = (nst + 1 == 3) ? 0 : nst + 1;
        }

        // epilogue: gates + state update
        #pragma unroll
        for (int half = 0; half < 2; half++) {
            int b = b0 + w*16 + laneR + half*8;
            #pragma unroll
            for (int uh = 0; uh < 2; uh++) {
                float cn[2], hn[2];
                #pragma unroll
                for (int du = 0; du < 2; du++) {
                    int q = half*2 + du;
                    float gi = acc[0*2+uh][q] + xv[half][uh*8+du*4+0];
                    float gf = acc[1*2+uh][q] + xv[half][uh*8+du*4+1];
                    float gg = acc[2*2+uh][q] + xv[half][uh*8+du*4+2];
                    float go = acc[3*2+uh][q] + xv[half][uh*8+du*4+3];
                    float is = 1.f/(1.f + __expf(-gi));
                    float fs = 1.f/(1.f + __expf(-gf));
                    float os = 1.f/(1.f + __expf(-go));
                    float gt = tanhf(gg);
                    int u = u0 + laneC*2 + uh*8 + du;
                    float co = cst[(size_t)b*Hsz + u];
                    cn[du] = fs*co + is*gt;
                    hn[du] = os*tanhf(cn[du]);
                }
                int u2 = u0 + laneC*2 + uh*8;
                size_t so = (size_t)b*Hsz + u2;
                *(float2*)(cst + so) = make_float2(cn[0], cn[1]);
                __half2 hp;
                hp.x = __float2half_rn(hn[0]);
                hp.y = __float2half_rn(hn[1]);
                *(__half2*)(Nx + so) = hp;
                *(__half2*)(seq + ((size_t)b*Tsz + t)*Hsz + u2) = hp;
            }
        }

        // ---- per-group grid barrier (32 CTAs sharing b0) ----
        if (t < Tsz - 1) {
            __threadfence();
            __syncthreads();
            if (tid == 0) {
                unsigned target = (unsigned)(t + 1);
                if (atomicAdd(&g_cnt[gid], 1u) == nGrp - 1u) {
                    atomicExch(&g_cnt[gid], 0u);
                    __threadfence();
                    atomicAdd(&g_gen[gid], 1u);
                } else {
                    unsigned v;
                    do { asm volatile("ld.acquire.gpu.global.u32 %0, [%1];" : "=r"(v) : "l"(&g_gen[gid])); }
                    while (v < target);
                }
            }
            __syncthreads();
            __threadfence();
        }
    }
}

// ---------------- small kernels ----------------
__global__ void conv_kernel(const float* __restrict__ s, __half* __restrict__ h, int n4){
    int i = blockIdx.x*blockDim.x + threadIdx.x;
    if (i < n4) {
        float4 v = ((const float4*)s)[i];
        __half2 a, b;
        a.x = __float2half_rn(v.x); a.y = __float2half_rn(v.y);
        b.x = __float2half_rn(v.z); b.y = __float2half_rn(v.w);
        ((__half2*)h)[i*2]   = a;
        ((__half2*)h)[i*2+1] = b;
    }
}
__global__ void embed_kernel(const int* __restrict__ x, const float* __restrict__ y,
                             const float* __restrict__ emb, const float* __restrict__ yW,
                             const float* __restrict__ yb, __half* __restrict__ o){
    int bt = blockIdx.x;            // bt = t*512 + b
    int t = bt >> 9, b = bt & 511;
    int h4 = threadIdx.x;           // 128 threads x 4 elems
    int tok = (t == 0) ? Vsz : x[b*Tsz + t - 1];
    float4 e = ((const float4*)(emb + (size_t)tok*Hsz))[h4];
    float4 wv = ((const float4*)yW)[h4];
    float4 bv = ((const float4*)yb)[h4];
    float yy = y[b];
    __half2 a, c;
    a.x = __float2half_rn(e.x + yy*wv.x + bv.x);
    a.y = __float2half_rn(e.y + yy*wv.y + bv.y);
    c.x = __float2half_rn(e.z + yy*wv.z + bv.z);
    c.y = __float2half_rn(e.w + yy*wv.w + bv.w);
    ((__half2*)(o + (size_t)bt*Hsz))[h4*2]   = a;
    ((__half2*)(o + (size_t)bt*Hsz))[h4*2+1] = c;
}
__global__ void zero_kernel(__half* hb, float* c){
    int i = blockIdx.x*blockDim.x + threadIdx.x;
    if (i < Bsz*Hsz) { c[i] = 0.f; hb[i] = __float2half(0.f); }
}

// ---------------- launch ----------------
extern "C" void kernel_launch(void* const* d_in, const int* in_sizes, int n_in,
                              void* d_out, int out_size)
{
    const int*   x    = (const int*)  d_in[0];
    const float* y    = (const float*)d_in[1];
    const float* emb  = (const float*)d_in[2];
    const float* yW   = (const float*)d_in[3];
    const float* yb   = (const float*)d_in[4];
    const float* Wih  = (const float*)d_in[5];
    const float* Whh  = (const float*)d_in[6];
    const float* bih  = (const float*)d_in[7];
    const float* bhh  = (const float*)d_in[8];
    const float* decW = (const float*)d_in[9];
    const float* decb = (const float*)d_in[10];
    float* out = (float*)d_out;

    __half *inp, *seq, *Wih_c, *Whh_c, *dW_c, *h0, *h1, *xgT;
    float *c;
    cudaGetSymbolAddress((void**)&inp,   g_inp);
    cudaGetSymbolAddress((void**)&seq,   g_seq);
    cudaGetSymbolAddress((void**)&xgT,   g_xgT);
    cudaGetSymbolAddress((void**)&h0,    g_h0);
    cudaGetSymbolAddress((void**)&h1,    g_h1);
    cudaGetSymbolAddress((void**)&c,     g_c);
    cudaGetSymbolAddress((void**)&Wih_c, g_Wih);
    cudaGetSymbolAddress((void**)&Whh_c, g_Whh);
    cudaGetSymbolAddress((void**)&dW_c,  g_dW);

    cudaFuncSetAttribute(gemm_mma, cudaFuncAttributeMaxDynamicSharedMemorySize, SMEMB);
    cudaFuncSetAttribute(lstm_persist, cudaFuncAttributeMaxDynamicSharedMemorySize, PS_SMEM);

    const int nW4 = 2*G4*Hsz/4;
    conv_kernel<<<(nW4+255)/256, 256>>>(Wih, Wih_c, nW4);
    conv_kernel<<<(nW4+255)/256, 256>>>(Whh, Whh_c, nW4);
    conv_kernel<<<(Vsz*Hsz/4+255)/256, 256>>>(decW, dW_c, Vsz*Hsz/4);
    embed_kernel<<<NBT, 128>>>(x, y, emb, yW, yb, inp);

    for (int l = 0; l < 2; l++) {
        const __half* Bmat = l ? seq : inp;
        // xgT[t][n][b] = Wih[n]·inp[t,b] + bih[n] + bhh[n]   (fp16 store)
        gemm_mma<<<dim3(G4/128, NBT/128), 256, SMEMB>>>(
            Wih_c + (size_t)l*G4*Hsz, Bmat,
            bih + l*G4, bhh + l*G4, nullptr, xgT, NBT, l ? 1 : 0, 1, 1);

        zero_kernel<<<(Bsz*Hsz+255)/256, 256>>>(h0, c);
        reset_bar<<<1, 4>>>();

        lstm_persist<<<dim3(Hsz/16, Bsz/128), 256, PS_SMEM>>>(
            xgT, Whh_c + (size_t)l*G4*Hsz, h0, h1, c, seq);
    }

    // decoder: out[(b*T+t)][v] = seq·decW^T + decb   (fp32 out)
    gemm_mma<<<dim3(Vsz/128, NBT/128), 256, SMEMB>>>(
        seq, dW_c, nullptr, nullptr, decb, out, Vsz, 0, 0, 0);
}